// round 7
// baseline (speedup 1.0000x reference)
#include <cuda_runtime.h>
#include <cstdint>

// Masked LeNet-C3 conv via TF32 mma.sync (HMMA) implicit GEMM on sm_103.
// x: [64,6,512,512] f32, W: [16,6,5,5] f32, b: [16] f32 -> out: [64,16,508,508] f32 (VALID 5x5)
//
// Per CTA (256 thr / 8 warps): output tile 64 px (x) x 8 rows (y), all 16 oc.
// Warp w computes row w: M=64 pixels (4 m16 tiles) x N=16 oc (2 n8 mmas), K-steps = (ic,ky),
// each K=8 = kx 0..4 real taps + 3 zero-weight pads. A-frags gathered from smem input tile,
// B-frags from a precomputed masked weight table. Inputs/weights RNE-rounded to tf32.

#define NIC 6
#define NOC 16
#define IH 512
#define IW 512
#define OH 508
#define OW 508
#define TILE_W 64
#define TILE_H 8
#define IN_ROWS 12          // TILE_H + 4
#define IN_W 72             // 64 + 4 halo + 4 zero pad (reads reach col 70)
#define NTHREADS 256

// LeNet-5 C3 connectivity
__host__ __device__ constexpr float conn(int ic, int oc) {
    constexpr int M[NIC][NOC] = {
        {1,0,0,0,1,1,1,0,0,1,1,1,1,0,1,1},
        {1,1,0,0,0,1,1,1,0,0,1,1,1,1,0,1},
        {1,1,1,0,0,0,1,1,1,0,0,1,0,1,1,1},
        {0,1,1,1,0,0,1,1,1,1,0,0,1,0,1,1},
        {0,0,1,1,1,0,0,1,1,1,1,0,1,1,0,1},
        {0,0,0,1,1,1,0,0,1,1,1,1,0,1,1,1},
    };
    return (float)M[ic][oc];
}

// round-to-nearest-even f32 -> tf32 bit pattern (10-bit mantissa)
__device__ __forceinline__ uint32_t f32_to_tf32(float f) {
    uint32_t u = __float_as_uint(f);
    uint32_t r = u + 0xFFFu + ((u >> 13) & 1u);
    return r & 0xFFFFE000u;
}

// D(16x8) += A(16x8) * B(8x8), tf32 inputs, f32 accumulate
__device__ __forceinline__ void mma_tf32(float* d, const uint32_t* a, const uint32_t* bb) {
    asm("mma.sync.aligned.m16n8k8.row.col.f32.tf32.tf32.f32 "
        "{%0,%1,%2,%3}, {%4,%5,%6,%7}, {%8,%9}, {%0,%1,%2,%3};"
        : "+f"(d[0]), "+f"(d[1]), "+f"(d[2]), "+f"(d[3])
        : "r"(a[0]), "r"(a[1]), "r"(a[2]), "r"(a[3]), "r"(bb[0]), "r"(bb[1]));
}

__global__ __launch_bounds__(NTHREADS, 3)
void conv_c3_mma(const float* __restrict__ x,
                 const float* __restrict__ W,
                 const float* __restrict__ b,
                 float* __restrict__ out)
{
    __shared__ float    s_in[NIC][IN_ROWS][IN_W];        // 5184 f = 20736 B (tf32-rounded)
    __shared__ uint32_t s_B[NIC * 5 * NOC * 8];          // 3840 u = 15360 B
    __shared__ float    s_b[NOC];

    const int tid  = threadIdx.x;
    const int lane = tid & 31;
    const int warp = tid >> 5;
    const int n    = blockIdx.z;
    const int by0  = blockIdx.y * TILE_H;
    const int bx0  = blockIdx.x * TILE_W;

    // ---- Input tile -> smem (tf32-rounded); zero outside image / pad cols ----
    #pragma unroll 1
    for (int idx = tid; idx < NIC * IN_ROWS * IN_W; idx += NTHREADS) {
        int ic  = idx / (IN_ROWS * IN_W);
        int rem = idx % (IN_ROWS * IN_W);
        int r   = rem / IN_W;
        int c   = rem % IN_W;
        int gy  = by0 + r;
        int gx  = bx0 + c;
        float v = 0.0f;
        if (c < TILE_W + 4 && gy < IH && gx < IW)
            v = __ldg(&x[(((size_t)n * NIC + ic) * IH + gy) * IW + gx]);
        s_in[ic][r][c] = __uint_as_float(f32_to_tf32(v));
    }

    // ---- Masked weight table: s_B[((ic*5+ky)*16 + oc)*8 + kx], kx>=5 -> 0 ----
    #pragma unroll 1
    for (int idx = tid; idx < NIC * 5 * NOC * 8; idx += NTHREADS) {
        int kx = idx & 7;
        int oc = (idx >> 3) & 15;
        int ky = (idx >> 7) % 5;
        int ic = idx / (5 * NOC * 8);
        float wv = 0.0f;
        if (kx < 5) wv = W[oc * (NIC * 25) + ic * 25 + ky * 5 + kx] * conn(ic, oc);
        s_B[idx] = f32_to_tf32(wv);
    }
    if (tid < NOC) s_b[tid] = b[tid];
    __syncthreads();

    // ---- Main loop: 30 K-steps (ic,ky), 8 HMMA each ----
    const int g    = lane >> 2;          // group id 0..7
    const int c4   = lane & 3;           // thread-in-group 0..3
    const int aoff = g + c4;             // A frag base column offset
    const int boff = g * 8 + c4;         // B frag base offset (low oc half)
    const int wy   = warp;               // output row within tile

    float acc[4][2][4];
    #pragma unroll
    for (int mt = 0; mt < 4; mt++)
        #pragma unroll
        for (int h = 0; h < 2; h++)
            #pragma unroll
            for (int i = 0; i < 4; i++) acc[mt][h][i] = 0.0f;

    #pragma unroll 1
    for (int ic = 0; ic < NIC; ic++) {
        #pragma unroll
        for (int ky = 0; ky < 5; ky++) {
            const uint32_t* Bp = s_B + (ic * 5 + ky) * (NOC * 8);
            uint32_t bL[2], bH[2];
            bL[0] = Bp[boff];          // B[k=c4][n=g]
            bL[1] = Bp[boff + 4];      // B[k=c4+4][n=g]
            bH[0] = Bp[64 + boff];     // oc 8..15
            bH[1] = Bp[64 + boff + 4];
            const float* rp = &s_in[ic][wy + ky][aoff];
            #pragma unroll
            for (int mt = 0; mt < 4; mt++) {
                uint32_t a[4];
                a[0] = __float_as_uint(rp[mt * 16 + 0]);   // [m=g   ][k=c4  ]
                a[1] = __float_as_uint(rp[mt * 16 + 8]);   // [m=g+8 ][k=c4  ]
                a[2] = __float_as_uint(rp[mt * 16 + 4]);   // [m=g   ][k=c4+4]
                a[3] = __float_as_uint(rp[mt * 16 + 12]);  // [m=g+8 ][k=c4+4]
                mma_tf32(acc[mt][0], a, bL);
                mma_tf32(acc[mt][1], a, bH);
            }
        }
    }

    // ---- Epilogue: D rows -> x, D cols -> oc ----
    const int y = by0 + wy;
    if (y < OH) {
        #pragma unroll
        for (int half = 0; half < 2; half++) {
            int oc0 = half * 8 + 2 * c4;
            float bo0 = s_b[oc0], bo1 = s_b[oc0 + 1];
            #pragma unroll
            for (int mt = 0; mt < 4; mt++) {
                int x0 = bx0 + mt * 16 + g;
                size_t base0 = (((size_t)n * NOC + oc0) * OH + y) * OW;
                size_t base1 = base0 + (size_t)OH * OW;
                if (x0 < OW) {
                    out[base0 + x0] = acc[mt][half][0] + bo0;
                    out[base1 + x0] = acc[mt][half][1] + bo1;
                }
                if (x0 + 8 < OW) {
                    out[base0 + x0 + 8] = acc[mt][half][2] + bo0;
                    out[base1 + x0 + 8] = acc[mt][half][3] + bo1;
                }
            }
        }
    }
}

extern "C" void kernel_launch(void* const* d_in, const int* in_sizes, int n_in,
                              void* d_out, int out_size) {
    const float* x = (const float*)d_in[0];
    const float* W = (const float*)d_in[1];
    const float* b = (const float*)d_in[2];
    float* out = (float*)d_out;

    const int n_batch = in_sizes[0] / (NIC * IH * IW);   // 64
    dim3 grid((OW + TILE_W - 1) / TILE_W,    // 8
              (OH + TILE_H - 1) / TILE_H,    // 64
              n_batch);                       // 64
    conv_c3_mma<<<grid, NTHREADS>>>(x, W, b, out);
}